// round 5
// baseline (speedup 1.0000x reference)
#include <cuda_runtime.h>
#include <cuda_bf16.h>
#include <mma.h>
#include <cmath>

using namespace nvcuda;
typedef __nv_bfloat16 bf16;

// Problem dims
constexpr int SEQ   = 2048;
constexpr int DE    = 2048;
constexpr int DMLP  = 8192;
constexpr int NH    = 16;

// Fused QKV layout (columns): [0,2048) q(h,e) | [2048,4096) k(h,e) |
// [4096,4111) v0 for heads 0..14 | 4111 pad | [4112,4240) v15 | pad to 4352
constexpr int NQKV   = 4352;
constexpr int VOFF0  = 4096;
constexpr int VOFF15 = 4112;
constexpr int YLD    = 160;   // ysmall padded K (143 real, rest zero)

// ---------------- device scratch (zero-initialized at module load) ----------
__device__ bf16  g_xn1b [SEQ*DE];
__device__ bf16  g_Bqkv [DE*NQKV];
__device__ float g_bqkv [NQKV];
__device__ bf16  g_qkv  [SEQ*NQKV];
__device__ float g_S    [SEQ*SEQ];
__device__ bf16  g_P    [SEQ*SEQ];
__device__ bf16  g_ys   [SEQ*YLD];    // cols 143..159 stay zero forever
__device__ bf16  g_Wob  [YLD*DE];
__device__ float g_x2   [SEQ*DE];
__device__ bf16  g_xn2b [SEQ*DE];
__device__ float g_xn2f [SEQ*DE];
__device__ bf16  g_W1b  [DE*DMLP];
__device__ bf16  g_h1   [SEQ*DMLP];
__device__ bf16  g_W2b  [DMLP*DE];

// ---------------- generic WMMA bf16 GEMM (fp32 accum) -----------------------
// C(MxN) = epilogue( alpha * A(MxK) @ B(KxN) + bias )
// transB=1 means B is stored row-major N x K (so B[k][n] = Bptr[n*ldb + k]).
// All of M,N multiples of 128; K multiple of 32. No guards.
// MODE: 0 = bf16 out (acc+bias)
//       1 = f32 out  (acc*alpha)          [scores]
//       2 = f32 out  (2*X + acc + bias)   [x2 = 2x + mh]
//       3 = bf16 out (gelu_tanh(acc+bias))
//       4 = f32 out  (X + X2n + acc + bias) [final residual]
template<int MODE>
__global__ __launch_bounds__(256)
void gemm_kernel(int M, int N, int K,
                 const bf16* __restrict__ A, int lda,
                 const bf16* __restrict__ B, int ldb, int transB,
                 void* __restrict__ C, int ldc,
                 const float* __restrict__ bias, float alpha,
                 const float* __restrict__ X, const float* __restrict__ X2n)
{
    __shared__ bf16  As[128][40];
    __shared__ bf16  Bs[32][136];
    __shared__ float stg[8][16][20];

    const int tid    = threadIdx.x;
    const int warpId = tid >> 5;
    const int lane   = tid & 31;
    const int wm     = warpId & 1;   // 2 warps along M
    const int wn     = warpId >> 1;  // 4 warps along N
    const int bm     = blockIdx.y * 128;
    const int bn     = blockIdx.x * 128;

    wmma::fragment<wmma::accumulator,16,16,16,float> acc[4][2];
    #pragma unroll
    for (int i = 0; i < 4; i++)
        #pragma unroll
        for (int j = 0; j < 2; j++)
            wmma::fill_fragment(acc[i][j], 0.f);

    const int ktiles = K >> 5;
    for (int kt = 0; kt < ktiles; kt++) {
        const int k0 = kt << 5;
        // A tile 128x32 : 2048 uint32 loads (2 bf16 each)
        #pragma unroll
        for (int jj = 0; jj < 8; jj++) {
            int u = tid + jj*256;
            int r = u >> 4, c2 = u & 15;
            *(unsigned*)(&As[r][c2*2]) =
                *(const unsigned*)(A + (size_t)(bm + r)*lda + k0 + c2*2);
        }
        if (!transB) {
            #pragma unroll
            for (int jj = 0; jj < 8; jj++) {
                int u = tid + jj*256;
                int r = u >> 6, c2 = u & 63;
                *(unsigned*)(&Bs[r][c2*2]) =
                    *(const unsigned*)(B + (size_t)(k0 + r)*ldb + bn + c2*2);
            }
        } else {
            #pragma unroll
            for (int jj = 0; jj < 8; jj++) {
                int u = tid + jj*256;
                int n = u >> 4, kp = u & 15;
                __nv_bfloat162 v =
                    *(const __nv_bfloat162*)(B + (size_t)(bn + n)*ldb + k0 + kp*2);
                Bs[kp*2][n]   = v.x;
                Bs[kp*2+1][n] = v.y;
            }
        }
        __syncthreads();

        #pragma unroll
        for (int ks = 0; ks < 32; ks += 16) {
            wmma::fragment<wmma::matrix_a,16,16,16,bf16,wmma::row_major> af[4];
            wmma::fragment<wmma::matrix_b,16,16,16,bf16,wmma::row_major> bfr[2];
            #pragma unroll
            for (int i = 0; i < 4; i++)
                wmma::load_matrix_sync(af[i], &As[wm*64 + i*16][ks], 40);
            #pragma unroll
            for (int j = 0; j < 2; j++)
                wmma::load_matrix_sync(bfr[j], &Bs[ks][wn*32 + j*16], 136);
            #pragma unroll
            for (int i = 0; i < 4; i++)
                #pragma unroll
                for (int j = 0; j < 2; j++)
                    wmma::mma_sync(acc[i][j], af[i], bfr[j], acc[i][j]);
        }
        __syncthreads();
    }

    // epilogue: stage each 16x16 fragment through smem, elementwise, store
    #pragma unroll
    for (int i = 0; i < 4; i++) {
        #pragma unroll
        for (int j = 0; j < 2; j++) {
            wmma::store_matrix_sync(&stg[warpId][0][0], acc[i][j], 20, wmma::mem_row_major);
            __syncwarp();
            #pragma unroll
            for (int e = 0; e < 8; e++) {
                int el = lane*8 + e;
                int r = el >> 4, c = el & 15;
                float v = stg[warpId][r][c] * alpha;
                int grow = bm + wm*64 + i*16 + r;
                int gcol = bn + wn*32 + j*16 + c;
                if (bias) v += bias[gcol];
                size_t idx = (size_t)grow * ldc + gcol;
                if constexpr (MODE == 0) {
                    ((bf16*)C)[idx] = __float2bfloat16(v);
                } else if constexpr (MODE == 1) {
                    ((float*)C)[idx] = v;
                } else if constexpr (MODE == 2) {
                    ((float*)C)[idx] = 2.f * X[idx] + v;
                } else if constexpr (MODE == 3) {
                    float g = 0.5f * v *
                        (1.f + tanhf(0.7978845608028654f * (v + 0.044715f*v*v*v)));
                    ((bf16*)C)[idx] = __float2bfloat16(g);
                } else {
                    ((float*)C)[idx] = X[idx] + X2n[idx] + v;
                }
            }
            __syncwarp();
        }
    }
}

// ---------------- layernorm (population std, jnp.std semantics) -------------
template<bool WF>
__global__ __launch_bounds__(256)
void ln_kernel(const float* __restrict__ X, const float* __restrict__ gamma,
               const float* __restrict__ beta,
               bf16* __restrict__ ob, float* __restrict__ of)
{
    int row = blockIdx.x, tid = threadIdx.x;
    const float* xr = X + (size_t)row * DE;
    float v[8], s = 0.f, sq = 0.f;
    #pragma unroll
    for (int i = 0; i < 8; i++) {
        v[i] = xr[tid + i*256];
        s  += v[i];
        sq += v[i]*v[i];
    }
    __shared__ float r1[256], r2[256];
    r1[tid] = s; r2[tid] = sq; __syncthreads();
    for (int o = 128; o > 0; o >>= 1) {
        if (tid < o) { r1[tid] += r1[tid+o]; r2[tid] += r2[tid+o]; }
        __syncthreads();
    }
    float mean = r1[0] * (1.f/DE);
    float var  = r2[0] * (1.f/DE) - mean*mean;
    float sd   = sqrtf(fmaxf(var, 0.f));
    if (sd == 0.f) sd = 1.f;
    float rs = 1.f / sd;
    #pragma unroll
    for (int i = 0; i < 8; i++) {
        int d = tid + i*256;
        float y = gamma[d] * ((v[i] - mean) * rs) + beta[d];
        ob[(size_t)row*DE + d] = __float2bfloat16(y);
        if (WF) of[(size_t)row*DE + d] = y;
    }
}

// ---------------- softmax + per-head reduction -------------------------------
// head < 15: out is a scalar per row:  ys[row][head] = (P . v0_head)
// head == 15: write full P row (bf16) for the PV GEMM
__global__ __launch_bounds__(256)
void softmax_kernel(const float* __restrict__ S, const bf16* __restrict__ qkv,
                    int head, bf16* __restrict__ P, bf16* __restrict__ ys)
{
    int row = blockIdx.x, tid = threadIdx.x;
    const float* Sr = S + (size_t)row * SEQ;
    float s[8];
    #pragma unroll
    for (int i = 0; i < 8; i++) s[i] = Sr[tid + i*256];
    float mx = s[0];
    #pragma unroll
    for (int i = 1; i < 8; i++) mx = fmaxf(mx, s[i]);
    __shared__ float red[256];
    red[tid] = mx; __syncthreads();
    for (int o = 128; o > 0; o >>= 1) {
        if (tid < o) red[tid] = fmaxf(red[tid], red[tid+o]);
        __syncthreads();
    }
    mx = red[0]; __syncthreads();

    float e[8], ls = 0.f;
    #pragma unroll
    for (int i = 0; i < 8; i++) { e[i] = expf(s[i] - mx); ls += e[i]; }
    red[tid] = ls; __syncthreads();
    for (int o = 128; o > 0; o >>= 1) {
        if (tid < o) red[tid] += red[tid+o];
        __syncthreads();
    }
    float tot = red[0]; __syncthreads();

    if (head == 15) {
        float inv = 1.f / tot;
        #pragma unroll
        for (int i = 0; i < 8; i++)
            P[(size_t)row*SEQ + tid + i*256] = __float2bfloat16(e[i] * inv);
    } else {
        float dot = 0.f;
        #pragma unroll
        for (int i = 0; i < 8; i++) {
            int m = tid + i*256;
            dot += e[i] * __bfloat162float(qkv[(size_t)m*NQKV + VOFF0 + head]);
        }
        red[tid] = dot; __syncthreads();
        for (int o = 128; o > 0; o >>= 1) {
            if (tid < o) red[tid] += red[tid+o];
            __syncthreads();
        }
        if (tid == 0)
            ys[(size_t)row*YLD + head] = __float2bfloat16(red[0] / tot);
    }
}

// ---------------- weight packing --------------------------------------------
__global__ void pack_qkv_kernel(const float* __restrict__ Wq,
                                const float* __restrict__ Wk,
                                const float* __restrict__ Wv,
                                bf16* __restrict__ Bq)
{
    const size_t total = (size_t)DE * NQKV;
    for (size_t idx = (size_t)blockIdx.x*blockDim.x + threadIdx.x;
         idx < total; idx += (size_t)gridDim.x*blockDim.x) {
        int d = (int)(idx / NQKV);
        int n = (int)(idx % NQKV);
        float w = 0.f;
        if (n < 2048) {
            w = Wq[(size_t)(n >> 7)*DE*128 + (size_t)d*128 + (n & 127)];
        } else if (n < 4096) {
            int m = n - 2048;
            w = Wk[(size_t)(m >> 7)*DE*128 + (size_t)d*128 + (m & 127)];
        } else if (n < 4111) {
            w = Wv[(size_t)(n - 4096)*DE*128 + (size_t)d*128];          // v[:,0] heads 0..14
        } else if (n >= VOFF15 && n < VOFF15 + 128) {
            w = Wv[(size_t)15*DE*128 + (size_t)d*128 + (n - VOFF15)];   // head 15 full
        }
        Bq[idx] = __float2bfloat16(w);
    }
}

__global__ void pack_bias_kernel(const float* __restrict__ bq,
                                 const float* __restrict__ bk,
                                 const float* __restrict__ bv,
                                 float* __restrict__ out)
{
    int n = blockIdx.x*blockDim.x + threadIdx.x;
    if (n >= NQKV) return;
    float b = 0.f;
    if (n < 2048)                           b = bq[n];
    else if (n < 4096)                      b = bk[n - 2048];
    else if (n < 4111)                      b = bv[(n - 4096)*128];
    else if (n >= VOFF15 && n < VOFF15+128) b = bv[15*128 + (n - VOFF15)];
    out[n] = b;
}

__global__ void pack_wo_kernel(const float* __restrict__ Wo, bf16* __restrict__ out)
{
    for (int idx = blockIdx.x*blockDim.x + threadIdx.x;
         idx < YLD*DE; idx += gridDim.x*blockDim.x) {
        int r = idx / DE;
        out[idx] = __float2bfloat16(r < 143 ? Wo[idx] : 0.f);
    }
}

__global__ void cvt_kernel(const float* __restrict__ in, bf16* __restrict__ out, size_t n)
{
    for (size_t i = (size_t)blockIdx.x*blockDim.x + threadIdx.x;
         i < n; i += (size_t)gridDim.x*blockDim.x)
        out[i] = __float2bfloat16(in[i]);
}

// ---------------- host orchestration ----------------------------------------
extern "C" void kernel_launch(void* const* d_in, const int* in_sizes, int n_in,
                              void* d_out, int out_size)
{
    (void)in_sizes; (void)n_in; (void)out_size;
    const float* x   = (const float*)d_in[0];
    const float* Wq  = (const float*)d_in[1];
    const float* bq  = (const float*)d_in[2];
    const float* Wk  = (const float*)d_in[3];
    const float* bk  = (const float*)d_in[4];
    const float* Wv  = (const float*)d_in[5];
    const float* bv  = (const float*)d_in[6];
    const float* Wo  = (const float*)d_in[7];
    const float* bo  = (const float*)d_in[8];
    const float* g1  = (const float*)d_in[9];
    const float* be1 = (const float*)d_in[10];
    const float* g2  = (const float*)d_in[11];
    const float* be2 = (const float*)d_in[12];
    const float* W1  = (const float*)d_in[13];
    const float* b1  = (const float*)d_in[14];
    const float* W2  = (const float*)d_in[15];
    const float* b2  = (const float*)d_in[16];
    float* out = (float*)d_out;

    bf16 *xn1b, *Bqkv, *qkv, *P, *ys, *Wob, *xn2b, *W1b, *h1, *W2b;
    float *bqkv, *S, *x2, *xn2f;
    cudaGetSymbolAddress((void**)&xn1b, g_xn1b);
    cudaGetSymbolAddress((void**)&Bqkv, g_Bqkv);
    cudaGetSymbolAddress((void**)&bqkv, g_bqkv);
    cudaGetSymbolAddress((void**)&qkv,  g_qkv);
    cudaGetSymbolAddress((void**)&S,    g_S);
    cudaGetSymbolAddress((void**)&P,    g_P);
    cudaGetSymbolAddress((void**)&ys,   g_ys);
    cudaGetSymbolAddress((void**)&Wob,  g_Wob);
    cudaGetSymbolAddress((void**)&x2,   g_x2);
    cudaGetSymbolAddress((void**)&xn2b, g_xn2b);
    cudaGetSymbolAddress((void**)&xn2f, g_xn2f);
    cudaGetSymbolAddress((void**)&W1b,  g_W1b);
    cudaGetSymbolAddress((void**)&h1,   g_h1);
    cudaGetSymbolAddress((void**)&W2b,  g_W2b);

    // Weight packing / conversion
    pack_qkv_kernel <<<4096, 256>>>(Wq, Wk, Wv, Bqkv);
    pack_bias_kernel<<<(NQKV + 255)/256, 256>>>(bq, bk, bv, bqkv);
    pack_wo_kernel  <<<640, 256>>>(Wo, Wob);
    cvt_kernel      <<<8192, 256>>>(W1, W1b, (size_t)DE * DMLP);
    cvt_kernel      <<<8192, 256>>>(W2, W2b, (size_t)DMLP * DE);

    // LN1
    ln_kernel<false><<<SEQ, 256>>>(x, g1, be1, xn1b, nullptr);

    dim3 blk(256);
    // Fused QKV: (2048 x 2048) @ (2048 x 4352) + bias -> bf16
    gemm_kernel<0><<<dim3(NQKV/128, SEQ/128), blk>>>(
        SEQ, NQKV, DE, xn1b, DE, Bqkv, NQKV, 0, qkv, NQKV, bqkv, 1.f, nullptr, nullptr);

    // Attention: per head S = q k^T / sqrt(128); softmax; fold heads 0..14 to scalar
    const float alphaS = 0.08838834764831845f;  // 1/sqrt(128)
    for (int h = 0; h < NH; h++) {
        gemm_kernel<1><<<dim3(SEQ/128, SEQ/128), blk>>>(
            SEQ, SEQ, 128, qkv + h*128, NQKV, qkv + 2048 + h*128, NQKV, 1,
            S, SEQ, nullptr, alphaS, nullptr, nullptr);
        softmax_kernel<<<SEQ, 256>>>(S, qkv, h, P, ys);
    }
    // Head 15: P(2048x2048) @ v15(2048x128) -> ysmall cols [15,143)
    gemm_kernel<0><<<dim3(1, SEQ/128), blk>>>(
        SEQ, 128, SEQ, P, SEQ, qkv + VOFF15, NQKV, 0,
        ys + 15, YLD, nullptr, 1.f, nullptr, nullptr);

    // mh + residual: x2 = 2x + ysmall @ Wo_top + bo   (K padded to 160)
    gemm_kernel<2><<<dim3(DE/128, SEQ/128), blk>>>(
        SEQ, DE, YLD, ys, YLD, Wob, DE, 0, x2, DE, bo, 1.f, x, nullptr);

    // LN2 (both bf16 for GEMM and f32 for the residual epilogue)
    ln_kernel<true><<<SEQ, 256>>>(x2, g2, be2, xn2b, xn2f);

    // MLP1: gelu(xn2 @ W1 + b1) -> bf16
    gemm_kernel<3><<<dim3(DMLP/128, SEQ/128), blk>>>(
        SEQ, DMLP, DE, xn2b, DE, W1b, DMLP, 0, h1, DMLP, b1, 1.f, nullptr, nullptr);

    // MLP2 + final residual: out = x2 + xn2 + h1 @ W2 + b2
    gemm_kernel<4><<<dim3(DE/128, SEQ/128), blk>>>(
        SEQ, DE, DMLP, h1, DMLP, W2b, DE, 0, out, DE, b2, 1.f, x2, xn2f);
}

// round 8
// speedup vs baseline: 1.6448x; 1.6448x over previous
#include <cuda_runtime.h>
#include <cuda_bf16.h>
#include <mma.h>
#include <cmath>

using namespace nvcuda;
typedef __nv_bfloat16 bf16;

// Problem dims
constexpr int SEQ   = 2048;
constexpr int DE    = 2048;
constexpr int DMLP  = 8192;
constexpr int NH    = 16;

// Fused QKV layout (columns): [0,2048) q(h,e) | [2048,4096) k(h,e) |
// [4096,4111) v0 for heads 0..14 | 4111 pad | [4112,4240) v15 | pad to 4352
constexpr int NQKV   = 4352;
constexpr int VOFF0  = 4096;
constexpr int VOFF15 = 4112;
constexpr int YLD    = 160;   // ysmall padded K (143 real, rest zero)

// ---------------- device scratch (zero-initialized at module load) ----------
__device__ __align__(256) bf16  g_xn1b [SEQ*DE];
__device__ __align__(256) bf16  g_Bqkv [DE*NQKV];
__device__ __align__(256) float g_bqkv [NQKV];
__device__ __align__(256) bf16  g_qkv  [SEQ*NQKV];
__device__ __align__(256) float g_S    [NH*SEQ*SEQ];   // 268MB, batched scores
__device__ __align__(256) bf16  g_P    [SEQ*SEQ];
__device__ __align__(256) bf16  g_ys   [SEQ*YLD];      // cols 143..159 stay zero
__device__ __align__(256) bf16  g_Wob  [YLD*DE];
__device__ __align__(256) float g_x2   [SEQ*DE];
__device__ __align__(256) bf16  g_xn2b [SEQ*DE];
__device__ __align__(256) float g_xn2f [SEQ*DE];
__device__ __align__(256) bf16  g_W1b  [DE*DMLP];
__device__ __align__(256) bf16  g_h1   [SEQ*DMLP];
__device__ __align__(256) bf16  g_W2b  [DMLP*DE];

// ---------------- cp.async helpers ------------------------------------------
__device__ __forceinline__ void cp16(void* dst, const void* src) {
    unsigned d = (unsigned)__cvta_generic_to_shared(dst);
    asm volatile("cp.async.cg.shared.global [%0], [%1], 16;\n" :: "r"(d), "l"(src));
}
__device__ __forceinline__ void cp_commit() {
    asm volatile("cp.async.commit_group;\n");
}
template<int N> __device__ __forceinline__ void cp_wait() {
    asm volatile("cp.async.wait_group %0;\n" :: "n"(N));
}

// ---------------- WMMA bf16 GEMM, double-buffered cp.async ------------------
// C(MxN) = epilogue( alpha * A(MxK) @ B(KxN) + bias ), per-z batch offsets.
// TRANSB: B is N x K row-major (B[k][n] = Bp[n*ldb + k]); smem tile is n-major
//         and the matrix_b fragment is loaded col_major.
// M,N multiples of 128; K multiple of 32. No guards.
// MODE: 0 bf16 out (acc+bias) | 1 f32 out (acc*alpha) | 2 f32 out (2X+acc+bias)
//       3 bf16 out gelu(acc+bias) | 4 f32 out (X+X2n+acc+bias)
template<int MODE, bool TRANSB>
__global__ __launch_bounds__(256)
void gemm_kernel(int M, int N, int K,
                 const bf16* __restrict__ A, int lda, long aBatch,
                 const bf16* __restrict__ B, int ldb, long bBatch,
                 void* __restrict__ C, int ldc, long cBatch,
                 const float* __restrict__ bias, float alpha,
                 const float* __restrict__ X, const float* __restrict__ X2n)
{
    __shared__ __align__(16) bf16 As[2][128][40];
    __shared__ __align__(16) bf16 Bs[2][TRANSB ? 128 : 32][TRANSB ? 40 : 136];

    const int tid    = threadIdx.x;
    const int warpId = tid >> 5;
    const int lane   = tid & 31;
    const int wm     = warpId & 1;
    const int wn     = warpId >> 1;
    const int bm     = blockIdx.y * 128;
    const int bn     = blockIdx.x * 128;
    const int z      = blockIdx.z;

    const bf16* Ag = A + (size_t)z * aBatch;
    const bf16* Bg = B + (size_t)z * bBatch;
    const size_t cOff = (size_t)z * cBatch;

    // chunk maps (2 x 16B per thread per tile)
    const int ar = tid >> 2,  ac = (tid & 3) * 8;           // A: 128 rows x 4 chunks
    const int ar2 = (tid + 256) >> 2, ac2 = ((tid + 256) & 3) * 8;
    // B non-trans: 32 rows x 16 chunks
    const int br = tid >> 4,  bc = (tid & 15) * 8;
    const int br2 = (tid + 256) >> 4, bc2 = ((tid + 256) & 15) * 8;

    auto issue = [&](int kt, int buf) {
        const int k0 = kt << 5;
        cp16(&As[buf][ar ][ac ], Ag + (size_t)(bm + ar )*lda + k0 + ac );
        cp16(&As[buf][ar2][ac2], Ag + (size_t)(bm + ar2)*lda + k0 + ac2);
        if (TRANSB) {
            cp16(&Bs[buf][ar ][ac ], Bg + (size_t)(bn + ar )*ldb + k0 + ac );
            cp16(&Bs[buf][ar2][ac2], Bg + (size_t)(bn + ar2)*ldb + k0 + ac2);
        } else {
            cp16(&Bs[buf][br ][bc ], Bg + (size_t)(k0 + br )*ldb + bn + bc );
            cp16(&Bs[buf][br2][bc2], Bg + (size_t)(k0 + br2)*ldb + bn + bc2);
        }
        cp_commit();
    };

    wmma::fragment<wmma::accumulator,16,16,16,float> acc[4][2];
    #pragma unroll
    for (int i = 0; i < 4; i++)
        #pragma unroll
        for (int j = 0; j < 2; j++)
            wmma::fill_fragment(acc[i][j], 0.f);

    const int ktiles = K >> 5;
    issue(0, 0);

    for (int kt = 0; kt < ktiles; kt++) {
        const int buf = kt & 1;
        if (kt + 1 < ktiles) { issue(kt + 1, buf ^ 1); cp_wait<1>(); }
        else                 { cp_wait<0>(); }
        __syncthreads();

        #pragma unroll
        for (int ks = 0; ks < 32; ks += 16) {
            wmma::fragment<wmma::matrix_a,16,16,16,bf16,wmma::row_major> af[4];
            #pragma unroll
            for (int i = 0; i < 4; i++)
                wmma::load_matrix_sync(af[i], &As[buf][wm*64 + i*16][ks], 40);
            if (TRANSB) {
                wmma::fragment<wmma::matrix_b,16,16,16,bf16,wmma::col_major> bfr[2];
                #pragma unroll
                for (int j = 0; j < 2; j++)
                    wmma::load_matrix_sync(bfr[j], &Bs[buf][wn*32 + j*16][ks], 40);
                #pragma unroll
                for (int i = 0; i < 4; i++)
                    #pragma unroll
                    for (int j = 0; j < 2; j++)
                        wmma::mma_sync(acc[i][j], af[i], bfr[j], acc[i][j]);
            } else {
                wmma::fragment<wmma::matrix_b,16,16,16,bf16,wmma::row_major> bfr[2];
                #pragma unroll
                for (int j = 0; j < 2; j++)
                    wmma::load_matrix_sync(bfr[j], &Bs[buf][ks][wn*32 + j*16], 136);
                #pragma unroll
                for (int i = 0; i < 4; i++)
                    #pragma unroll
                    for (int j = 0; j < 2; j++)
                        wmma::mma_sync(acc[i][j], af[i], bfr[j], acc[i][j]);
            }
        }
        __syncthreads();
    }

    // epilogue: stage each 16x16 fragment through smem (overlaid on As)
    float* stg = ((float*)&As[0][0][0]) + warpId * 320;   // 16x20 per warp
    #pragma unroll
    for (int i = 0; i < 4; i++) {
        #pragma unroll
        for (int j = 0; j < 2; j++) {
            wmma::store_matrix_sync(stg, acc[i][j], 20, wmma::mem_row_major);
            __syncwarp();
            #pragma unroll
            for (int e = 0; e < 8; e++) {
                int el = lane*8 + e;
                int r = el >> 4, c = el & 15;
                float v = stg[r*20 + c] * alpha;
                int grow = bm + wm*64 + i*16 + r;
                int gcol = bn + wn*32 + j*16 + c;
                if (bias) v += bias[gcol];
                size_t idx = cOff + (size_t)grow * ldc + gcol;
                if constexpr (MODE == 0) {
                    ((bf16*)C)[idx] = __float2bfloat16(v);
                } else if constexpr (MODE == 1) {
                    ((float*)C)[idx] = v;
                } else if constexpr (MODE == 2) {
                    ((float*)C)[idx] = 2.f * X[idx] + v;
                } else if constexpr (MODE == 3) {
                    float g = 0.5f * v *
                        (1.f + tanhf(0.7978845608028654f * (v + 0.044715f*v*v*v)));
                    ((bf16*)C)[idx] = __float2bfloat16(g);
                } else {
                    ((float*)C)[idx] = X[idx] + X2n[idx] + v;
                }
            }
            __syncwarp();
        }
    }
}

// ---------------- layernorm (population std, jnp.std semantics) -------------
template<bool WF>
__global__ __launch_bounds__(256)
void ln_kernel(const float* __restrict__ X, const float* __restrict__ gamma,
               const float* __restrict__ beta,
               bf16* __restrict__ ob, float* __restrict__ of)
{
    int row = blockIdx.x, tid = threadIdx.x;
    const float* xr = X + (size_t)row * DE;
    float v[8], s = 0.f, sq = 0.f;
    #pragma unroll
    for (int i = 0; i < 8; i++) {
        v[i] = xr[tid + i*256];
        s  += v[i];
        sq += v[i]*v[i];
    }
    __shared__ float r1[256], r2[256];
    r1[tid] = s; r2[tid] = sq; __syncthreads();
    for (int o = 128; o > 0; o >>= 1) {
        if (tid < o) { r1[tid] += r1[tid+o]; r2[tid] += r2[tid+o]; }
        __syncthreads();
    }
    float mean = r1[0] * (1.f/DE);
    float var  = r2[0] * (1.f/DE) - mean*mean;
    float sd   = sqrtf(fmaxf(var, 0.f));
    if (sd == 0.f) sd = 1.f;
    float rs = 1.f / sd;
    #pragma unroll
    for (int i = 0; i < 8; i++) {
        int d = tid + i*256;
        float y = gamma[d] * ((v[i] - mean) * rs) + beta[d];
        ob[(size_t)row*DE + d] = __float2bfloat16(y);
        if (WF) of[(size_t)row*DE + d] = y;
    }
}

// ---------------- batched softmax + per-head reduction ----------------------
// head < 15: ys[row][head] = softmax(S_h[row]) . v0_head
// head == 15: write full P row (bf16) for the PV GEMM
__global__ __launch_bounds__(256)
void softmax_kernel(const float* __restrict__ S, const bf16* __restrict__ qkv,
                    bf16* __restrict__ P, bf16* __restrict__ ys)
{
    int row = blockIdx.x, head = blockIdx.y, tid = threadIdx.x;
    const float* Sr = S + (size_t)head*SEQ*SEQ + (size_t)row*SEQ;
    float s[8];
    #pragma unroll
    for (int i = 0; i < 8; i++) s[i] = Sr[tid + i*256];
    float mx = s[0];
    #pragma unroll
    for (int i = 1; i < 8; i++) mx = fmaxf(mx, s[i]);
    __shared__ float red[256];
    red[tid] = mx; __syncthreads();
    for (int o = 128; o > 0; o >>= 1) {
        if (tid < o) red[tid] = fmaxf(red[tid], red[tid+o]);
        __syncthreads();
    }
    mx = red[0]; __syncthreads();

    float e[8], ls = 0.f;
    #pragma unroll
    for (int i = 0; i < 8; i++) { e[i] = expf(s[i] - mx); ls += e[i]; }
    red[tid] = ls; __syncthreads();
    for (int o = 128; o > 0; o >>= 1) {
        if (tid < o) red[tid] += red[tid+o];
        __syncthreads();
    }
    float tot = red[0]; __syncthreads();

    if (head == 15) {
        float inv = 1.f / tot;
        #pragma unroll
        for (int i = 0; i < 8; i++)
            P[(size_t)row*SEQ + tid + i*256] = __float2bfloat16(e[i] * inv);
    } else {
        float dot = 0.f;
        #pragma unroll
        for (int i = 0; i < 8; i++) {
            int m = tid + i*256;
            dot += e[i] * __bfloat162float(qkv[(size_t)m*NQKV + VOFF0 + head]);
        }
        red[tid] = dot; __syncthreads();
        for (int o = 128; o > 0; o >>= 1) {
            if (tid < o) red[tid] += red[tid+o];
            __syncthreads();
        }
        if (tid == 0)
            ys[(size_t)row*YLD + head] = __float2bfloat16(red[0] / tot);
    }
}

// ---------------- weight packing --------------------------------------------
__global__ void pack_qkv_kernel(const float* __restrict__ Wq,
                                const float* __restrict__ Wk,
                                const float* __restrict__ Wv,
                                bf16* __restrict__ Bq)
{
    const size_t total = (size_t)DE * NQKV;
    for (size_t idx = (size_t)blockIdx.x*blockDim.x + threadIdx.x;
         idx < total; idx += (size_t)gridDim.x*blockDim.x) {
        int d = (int)(idx / NQKV);
        int n = (int)(idx % NQKV);
        float w = 0.f;
        if (n < 2048) {
            w = Wq[(size_t)(n >> 7)*DE*128 + (size_t)d*128 + (n & 127)];
        } else if (n < 4096) {
            int m = n - 2048;
            w = Wk[(size_t)(m >> 7)*DE*128 + (size_t)d*128 + (m & 127)];
        } else if (n < 4111) {
            w = Wv[(size_t)(n - 4096)*DE*128 + (size_t)d*128];
        } else if (n >= VOFF15 && n < VOFF15 + 128) {
            w = Wv[(size_t)15*DE*128 + (size_t)d*128 + (n - VOFF15)];
        }
        Bq[idx] = __float2bfloat16(w);
    }
}

__global__ void pack_bias_kernel(const float* __restrict__ bq,
                                 const float* __restrict__ bk,
                                 const float* __restrict__ bv,
                                 float* __restrict__ out)
{
    int n = blockIdx.x*blockDim.x + threadIdx.x;
    if (n >= NQKV) return;
    float b = 0.f;
    if (n < 2048)                           b = bq[n];
    else if (n < 4096)                      b = bk[n - 2048];
    else if (n < 4111)                      b = bv[(n - 4096)*128];
    else if (n >= VOFF15 && n < VOFF15+128) b = bv[15*128 + (n - VOFF15)];
    out[n] = b;
}

__global__ void pack_wo_kernel(const float* __restrict__ Wo, bf16* __restrict__ out)
{
    for (int idx = blockIdx.x*blockDim.x + threadIdx.x;
         idx < YLD*DE; idx += gridDim.x*blockDim.x) {
        int r = idx / DE;
        out[idx] = __float2bfloat16(r < 143 ? Wo[idx] : 0.f);
    }
}

// vectorized fp32 -> bf16 (4 elems / thread-iter: 16B load, 8B store)
__global__ void cvt_kernel(const float4* __restrict__ in, uint2* __restrict__ out,
                           size_t n4)
{
    for (size_t i = (size_t)blockIdx.x*blockDim.x + threadIdx.x;
         i < n4; i += (size_t)gridDim.x*blockDim.x) {
        float4 v = in[i];
        __nv_bfloat162 a = __floats2bfloat162_rn(v.x, v.y);
        __nv_bfloat162 b = __floats2bfloat162_rn(v.z, v.w);
        uint2 o;
        o.x = *(unsigned*)&a;
        o.y = *(unsigned*)&b;
        out[i] = o;
    }
}

// ---------------- host orchestration ----------------------------------------
extern "C" void kernel_launch(void* const* d_in, const int* in_sizes, int n_in,
                              void* d_out, int out_size)
{
    (void)in_sizes; (void)n_in; (void)out_size;
    const float* x   = (const float*)d_in[0];
    const float* Wq  = (const float*)d_in[1];
    const float* bq  = (const float*)d_in[2];
    const float* Wk  = (const float*)d_in[3];
    const float* bk  = (const float*)d_in[4];
    const float* Wv  = (const float*)d_in[5];
    const float* bv  = (const float*)d_in[6];
    const float* Wo  = (const float*)d_in[7];
    const float* bo  = (const float*)d_in[8];
    const float* g1  = (const float*)d_in[9];
    const float* be1 = (const float*)d_in[10];
    const float* g2  = (const float*)d_in[11];
    const float* be2 = (const float*)d_in[12];
    const float* W1  = (const float*)d_in[13];
    const float* b1  = (const float*)d_in[14];
    const float* W2  = (const float*)d_in[15];
    const float* b2  = (const float*)d_in[16];
    float* out = (float*)d_out;

    bf16 *xn1b, *Bqkv, *qkv, *P, *ys, *Wob, *xn2b, *W1b, *h1, *W2b;
    float *bqkv, *S, *x2, *xn2f;
    cudaGetSymbolAddress((void**)&xn1b, g_xn1b);
    cudaGetSymbolAddress((void**)&Bqkv, g_Bqkv);
    cudaGetSymbolAddress((void**)&bqkv, g_bqkv);
    cudaGetSymbolAddress((void**)&qkv,  g_qkv);
    cudaGetSymbolAddress((void**)&S,    g_S);
    cudaGetSymbolAddress((void**)&P,    g_P);
    cudaGetSymbolAddress((void**)&ys,   g_ys);
    cudaGetSymbolAddress((void**)&Wob,  g_Wob);
    cudaGetSymbolAddress((void**)&x2,   g_x2);
    cudaGetSymbolAddress((void**)&xn2b, g_xn2b);
    cudaGetSymbolAddress((void**)&xn2f, g_xn2f);
    cudaGetSymbolAddress((void**)&W1b,  g_W1b);
    cudaGetSymbolAddress((void**)&h1,   g_h1);
    cudaGetSymbolAddress((void**)&W2b,  g_W2b);

    // Weight packing / conversion
    pack_qkv_kernel <<<4096, 256>>>(Wq, Wk, Wv, Bqkv);
    pack_bias_kernel<<<(NQKV + 255)/256, 256>>>(bq, bk, bv, bqkv);
    pack_wo_kernel  <<<640, 256>>>(Wo, Wob);
    cvt_kernel      <<<4096, 256>>>((const float4*)W1, (uint2*)W1b,
                                    (size_t)DE * DMLP / 4);
    cvt_kernel      <<<4096, 256>>>((const float4*)W2, (uint2*)W2b,
                                    (size_t)DMLP * DE / 4);

    // LN1
    ln_kernel<false><<<SEQ, 256>>>(x, g1, be1, xn1b, nullptr);

    dim3 blk(256);
    // Fused QKV: (2048 x 2048) @ (2048 x 4352) + bias -> bf16
    gemm_kernel<0,false><<<dim3(NQKV/128, SEQ/128), blk>>>(
        SEQ, NQKV, DE, xn1b, DE, 0, Bqkv, NQKV, 0, qkv, NQKV, 0,
        bqkv, 1.f, nullptr, nullptr);

    // Batched scores: S[h] = q_h k_h^T / sqrt(128)  (one launch, z = head)
    const float alphaS = 0.08838834764831845f;
    gemm_kernel<1,true><<<dim3(SEQ/128, SEQ/128, NH), blk>>>(
        SEQ, SEQ, 128, qkv, NQKV, 128, qkv + 2048, NQKV, 128,
        S, SEQ, (long)SEQ*SEQ, nullptr, alphaS, nullptr, nullptr);

    // Batched softmax: heads 0..14 fold to scalar, head 15 writes P
    softmax_kernel<<<dim3(SEQ, NH), 256>>>(S, qkv, P, ys);

    // Head 15: P(2048x2048) @ v15(2048x128) -> ysmall cols [15,143)
    gemm_kernel<0,false><<<dim3(1, SEQ/128), blk>>>(
        SEQ, 128, SEQ, P, SEQ, 0, qkv + VOFF15, NQKV, 0,
        ys + 15, YLD, 0, nullptr, 1.f, nullptr, nullptr);

    // mh + residual: x2 = 2x + ysmall @ Wo_top + bo   (K padded to 160)
    gemm_kernel<2,false><<<dim3(DE/128, SEQ/128), blk>>>(
        SEQ, DE, YLD, ys, YLD, 0, Wob, DE, 0, x2, DE, 0,
        bo, 1.f, x, nullptr);

    // LN2 (bf16 for GEMM + f32 for the residual epilogue)
    ln_kernel<true><<<SEQ, 256>>>(x2, g2, be2, xn2b, xn2f);

    // MLP1: gelu(xn2 @ W1 + b1) -> bf16
    gemm_kernel<3,false><<<dim3(DMLP/128, SEQ/128), blk>>>(
        SEQ, DMLP, DE, xn2b, DE, 0, W1b, DMLP, 0, h1, DMLP, 0,
        b1, 1.f, nullptr, nullptr);

    // MLP2 + final residual: out = x2 + xn2 + h1 @ W2 + b2
    gemm_kernel<4,false><<<dim3(DE/128, SEQ/128), blk>>>(
        SEQ, DE, DMLP, h1, DMLP, 0, W2b, DE, 0, out, DE, 0,
        b2, 1.f, x2, xn2f);
}